// round 14
// baseline (speedup 1.0000x reference)
#include <cuda_runtime.h>
#include <cstdint>

#define BB 4
#define CC 4
#define HH 96
#define WW 96
#define HW (HH*WW)
#define CSZ 8             // cluster size = slices per image
#define SR 12             // rows per slice
#define NTHR 768
#define NWARP (NTHR/32)
#define NBLK (BB*CSZ)
#define NSPAN (SR*WW/32)  // 36 ballot spans per slice

__device__ volatile float g_res[BB];   // per-image sqrt(d2), written by rank0
__device__ unsigned g_tick;            // cross-image ticket; last resets

#define CLUSTER_SYNC() do { \
    asm volatile("barrier.cluster.arrive.aligned;" ::: "memory"); \
    asm volatile("barrier.cluster.wait.aligned;" ::: "memory"); } while (0)

__device__ __forceinline__ unsigned smem_u32(const void* p) {
    unsigned a;
    asm("{ .reg .u64 t; cvta.to.shared.u64 t, %1; cvt.u32.u64 %0, t; }"
        : "=r"(a) : "l"(p));
    return a;
}
__device__ __forceinline__ unsigned cluster_rank() {
    unsigned r; asm("mov.u32 %0, %%cluster_ctarank;" : "=r"(r)); return r;
}
__device__ __forceinline__ void st_cluster_u64(unsigned local_addr, unsigned rank,
                                               unsigned long long v) {
    unsigned ra;
    asm("mapa.shared::cluster.u32 %0, %1, %2;" : "=r"(ra) : "r"(local_addr), "r"(rank));
    asm volatile("st.shared::cluster.u64 [%0], %1;" :: "r"(ra), "l"(v) : "memory");
}
__device__ __forceinline__ void mbar_init(unsigned addr, unsigned cnt) {
    asm volatile("mbarrier.init.shared.b64 [%0], %1;" :: "r"(addr), "r"(cnt) : "memory");
}
// remote arrive on rank's copy of the barrier; release at cluster scope orders
// our preceding st.shared::cluster mailbox store
__device__ __forceinline__ void mbar_arrive_rank(unsigned local_addr, unsigned rank) {
    unsigned ra;
    asm("mapa.shared::cluster.u32 %0, %1, %2;" : "=r"(ra) : "r"(local_addr), "r"(rank));
    asm volatile("mbarrier.arrive.release.cluster.shared::cluster.b64 _, [%0];"
                 :: "r"(ra) : "memory");
}
__device__ __forceinline__ void mbar_wait_parity0_cluster(unsigned addr) {
    asm volatile(
        "{\n\t"
        ".reg .pred P1;\n\t"
        "WAIT_LOOP_%=:\n\t"
        "mbarrier.try_wait.parity.acquire.cluster.shared::cta.b64 P1, [%0], 0, 0x989680;\n\t"
        "@P1 bra.uni WAIT_DONE_%=;\n\t"
        "bra.uni WAIT_LOOP_%=;\n\t"
        "WAIT_DONE_%=:\n\t"
        "}" :: "r"(addr) : "memory");
}

// horizontal min-plus with sound early exit: d2 = min_jp (j-jp)^2 + g[jp]^2
__device__ __forceinline__ int hmin(const unsigned char* g, int j) {
    int g0 = g[j];
    int best = g0 * g0;
    #pragma unroll 1
    for (int r = 1; r < WW; r++) {
        int rr = r * r;
        if (rr >= best) break;
        if (j - r >= 0) { int a = g[j - r]; best = min(best, rr + a*a); }
        if (j + r < WW) { int a = g[j + r]; best = min(best, rr + a*a); }
    }
    return best;
}

__device__ __forceinline__ int amax4(float v0, float v1, float v2, float v3) {
    int c = 0; float b = v0;
    if (v1 > b) { b = v1; c = 1; }
    if (v2 > b) { b = v2; c = 2; }
    if (v3 > b) { b = v3; c = 3; }
    return c;
}

__global__ __launch_bounds__(NTHR, 1) __cluster_dims__(CSZ, 1, 1)
void k_all(const float* __restrict__ outp, const int* __restrict__ tgt,
           float* __restrict__ out) {
    __shared__ unsigned char labP[(SR+2)*WW];
    __shared__ unsigned char labT[(SR+2)*WW];
    // full-image row-major masks: rmPT[row*3 + word] = P bits (lo32) | T bits (hi32)
    __shared__ unsigned long long rmPT[HH*3];
    __shared__ unsigned char gPr[SR*WW];
    __shared__ unsigned char gTr[SR*WW];
    __shared__ unsigned long long mail[CSZ];   // rank0's result mailbox
    __shared__ alignas(8) unsigned long long mbarS;
    __shared__ int sMaxF, sMaxB;

    const int bb  = blockIdx.x;
    const int b   = bb / CSZ;
    const int s   = cluster_rank();          // slice within image
    const int tid = threadIdx.x;
    const int wid = tid >> 5;
    const int lid = tid & 31;

    if (tid == 0) {
        sMaxF = -1; sMaxB = -1;
        if (s == 0) mbar_init(smem_u32(&mbarS), CSZ);
    }

    // ===== phase A: float4 argmax + labels for rows rbase..rbase+13 (halo) =====
    const int rbase = s*SR - 1;
    const float* basep = outp + (size_t)b * CC * HW;
    const int*   tb    = tgt + (size_t)b * HW;
    if (tid < (SR+2) * (WW/4)) {             // 14 rows * 24 float4 groups = 336
        int li = tid / (WW/4), jv = tid % (WW/4);
        int gi = rbase + li;
        if (gi >= 0 && gi < HH) {
            int idx = gi*WW + jv*4;
            float4 a0 = *(const float4*)(basep + idx);
            float4 a1 = *(const float4*)(basep + idx + HW);
            float4 a2 = *(const float4*)(basep + idx + 2*HW);
            float4 a3 = *(const float4*)(basep + idx + 3*HW);
            int4  t4  = *(const int4*)(tb + idx);
            unsigned lp = (unsigned)amax4(a0.x, a1.x, a2.x, a3.x)
                        | ((unsigned)amax4(a0.y, a1.y, a2.y, a3.y) << 8)
                        | ((unsigned)amax4(a0.z, a1.z, a2.z, a3.z) << 16)
                        | ((unsigned)amax4(a0.w, a1.w, a2.w, a3.w) << 24);
            unsigned lt = (unsigned)t4.x | ((unsigned)t4.y << 8)
                        | ((unsigned)t4.z << 16) | ((unsigned)t4.w << 24);
            *(unsigned*)&labP[li*WW + jv*4] = lp;
            *(unsigned*)&labT[li*WW + jv*4] = lt;
        }
    }
    __syncthreads();

    // ===== phase B: boundary ballots; lanes 0..7 fan the u64 out to 8 ranks =====
    #pragma unroll
    for (int it = 0; it < 2; it++) {
        int sp = it*NWARP + wid;             // span id; 2nd iter: 12 warps idle
        if (sp < NSPAN) {
            int r  = sp / 3;                 // local row 0..11
            int w  = sp % 3;                 // 32-column word index
            int j  = w*32 + lid;
            int gi = s*SR + r;
            int o  = (r + 1)*WW + j;
            int lp = labP[o], lt = labT[o];
            int mp = 0, mt = 0;
            if (gi > 0)    { mp |= labP[o-WW] != lp; mt |= labT[o-WW] != lt; }
            if (gi < HH-1) { mp |= labP[o+WW] != lp; mt |= labT[o+WW] != lt; }
            if (j > 0)     { mp |= labP[o-1]  != lp; mt |= labT[o-1]  != lt; }
            if (j < WW-1)  { mp |= labP[o+1]  != lp; mt |= labT[o+1]  != lt; }
            unsigned wp = __ballot_sync(0xFFFFFFFFu, mp);
            unsigned wt = __ballot_sync(0xFFFFFFFFu, mt);
            if (lid < CSZ) {                 // 8 lanes push in parallel, 1 store each
                unsigned long long v = (unsigned long long)wp
                                     | ((unsigned long long)wt << 32);
                st_cluster_u64(smem_u32(&rmPT[gi*3 + w]), (unsigned)lid, v);
            }
        }
    }

    // ===== single cluster barrier: orders all mask pushes + mbarrier init =====
    CLUSTER_SYNC();

    // ===== phase F+G fused: warp w owns row w entirely (3 px/lane) =====
    int maxF = -1, maxB = -1;
    if (wid < SR) {
        const int r  = wid;
        const int gi = s*SR + r;
        unsigned char* gProw = gPr + r*WW;
        unsigned char* gTrow = gTr + r*WW;
        int dPk[3], dTk[3];
        #pragma unroll
        for (int k = 0; k < 3; k++) {
            int j  = k*32 + lid;
            int bit = lid;
            unsigned long long w0 = rmPT[gi*3 + k];
            int dP = ((unsigned)(w0 >> bit) & 1u) ? 0 : 255;
            int dT = ((unsigned)(w0 >> (bit + 32)) & 1u) ? 0 : 255;
            #pragma unroll 1
            for (int rr = 1; (dP == 255) | (dT == 255); rr++) {
                bool anyRow = false;
                unsigned long long both = 0;
                if (gi - rr >= 0) { both  = rmPT[(gi-rr)*3 + k]; anyRow = true; }
                if (gi + rr < HH) { both |= rmPT[(gi+rr)*3 + k]; anyRow = true; }
                if (!anyRow) break;
                if (dP == 255 && (((unsigned)(both >> bit)) & 1u)) dP = rr;
                if (dT == 255 && (((unsigned)(both >> (bit + 32))) & 1u)) dT = rr;
            }
            gProw[j] = (unsigned char)dP;
            gTrow[j] = (unsigned char)dT;
            dPk[k] = dP; dTk[k] = dT;
        }
        __syncwarp();
        #pragma unroll
        for (int k = 0; k < 3; k++) {
            int j = k*32 + lid;
            if (dPk[k] == 0) maxF = max(maxF, hmin(gTrow, j));  // pred -> tgt
            if (dTk[k] == 0) maxB = max(maxB, hmin(gProw, j));  // tgt -> pred
        }
    }

    // ===== phase H: warp reduce -> smem atomicMax -> mailbox to rank0 =====
    #pragma unroll
    for (int sh = 16; sh > 0; sh >>= 1) {
        maxF = max(maxF, __shfl_xor_sync(0xFFFFFFFFu, maxF, sh));
        maxB = max(maxB, __shfl_xor_sync(0xFFFFFFFFu, maxB, sh));
    }
    if (lid == 0) {
        if (maxF >= 0) atomicMax(&sMaxF, maxF);
        if (maxB >= 0) atomicMax(&sMaxB, maxB);
    }
    __syncthreads();

    if (tid == 0) {
        // pack (+1 bias keeps components non-negative)
        unsigned long long v = ((unsigned long long)(unsigned)(sMaxF + 1) << 32)
                             | (unsigned)(sMaxB + 1);
        st_cluster_u64(smem_u32(&mail[s]), 0u, v);
        mbar_arrive_rank(smem_u32(&mbarS), 0u);
        if (s == 0) {
            mbar_wait_parity0_cluster(smem_u32(&mbarS));
            int f = 0, w = 0;
            #pragma unroll
            for (int k = 0; k < CSZ; k++) {
                unsigned long long m = mail[k];
                f = max(f, (int)(unsigned)(m >> 32));
                w = max(w, (int)(unsigned)(m & 0xFFFFFFFFu));
            }
            int vmax = max(max(f, w) - 1, 0);      // undo bias
            float d2 = (vmax >= 50000) ? 1e10f : (float)vmax;  // empty-set sentinel
            g_res[b] = sqrtf(d2);
            __threadfence();
            unsigned t2 = atomicAdd(&g_tick, 1u);
            if (t2 == BB - 1) {                    // last image writes the mean
                float sum = 0.0f;
                #pragma unroll
                for (int k = 0; k < BB; k++) sum += g_res[k];  // fixed order
                out[0] = sum * (1.0f / BB);
                g_tick = 0;                        // reset for next replay
            }
        }
    }
}

extern "C" void kernel_launch(void* const* d_in, const int* in_sizes, int n_in,
                              void* d_out, int out_size) {
    const float* outp = (const float*)d_in[0];   // [B,C,H,W] fp32
    const int*   tgt  = (const int*)d_in[1];     // [B,H,W] int32
    k_all<<<NBLK, NTHR>>>(outp, tgt, (float*)d_out);
}